// round 8
// baseline (speedup 1.0000x reference)
#include <cuda_runtime.h>
#include <cuda_fp16.h>
#include <cstdint>

#define IM_HW   16384          // 128*128 pixels
#define BC      64             // B*C channels
#define NB      10980          // 183*60 HT bins
#define NV      983040         // votes (= 3840*256 exactly)
#define CAP     256            // per-bin capacity (mean 89.5, sigma 9.4 -> 17 sigma)
#define TBLK    512            // transpose blocks in fused prep kernel
#define SCAPS   192            // smem-staged pairs per bin (mean+11 sigma)

__device__ __forceinline__ __half2 u2h2(unsigned u) {
    union { unsigned u; __half2 h; } c; c.u = u; return c.h;
}
__device__ __forceinline__ unsigned h22u(__half2 h) {
    union { unsigned u; __half2 h; } c; c.h = h; return c.u;
}

// -------- persistent scratch (__device__ globals; zero-initialized) --------
__device__ uint4 d_xh[IM_HW * 8];             // fp16 image [pix][64ch] = 128B/row (2 MB)
__device__ int   d_cursor[NB];                // per-bin count; re-zeroed by gather
__device__ uint2 d_pairs[NB * CAP];           // (pix*128, bits(w_fp32)) per slot (22.5 MB)
__device__ int   d_ovf_cnt;
__device__ uint4 d_ovf[4096];                 // overflow spill (pixoff, wbits, bin, 0)

// -------- 1. fused prep: transpose+fp16 (blocks 0..511) || fill (blocks 512+) --------
__global__ void __launch_bounds__(256) prep_kernel(const float* __restrict__ im,
                                                   const float* __restrict__ vm) {
    if (blockIdx.x < TBLK) {
        __shared__ float tile[32][68];        // pitch 272B -> float4-aligned rows
        int pixbase = blockIdx.x * 32;
        int t  = threadIdx.x;
        int tx = t & 31;
        int ty = t >> 5;
        #pragma unroll
        for (int b0 = 0; b0 < BC; b0 += 8)
            tile[tx][b0 + ty] = im[(b0 + ty) * IM_HW + pixbase + tx];   // coalesced
        __syncthreads();
        int p  = t >> 3;
        int c0 = (t & 7) * 8;
        float4 a = *(float4*)&tile[p][c0];
        float4 b = *(float4*)&tile[p][c0 + 4];
        uint4 hv;
        hv.x = h22u(__float22half2_rn(make_float2(a.x, a.y)));
        hv.y = h22u(__float22half2_rn(make_float2(a.z, a.w)));
        hv.z = h22u(__float22half2_rn(make_float2(b.x, b.y)));
        hv.w = h22u(__float22half2_rn(make_float2(b.z, b.w)));
        *(uint4*)((char*)d_xh + (pixbase + p) * 128 + c0 * 2) = hv;
    } else {
        int v = (blockIdx.x - TBLK) * 256 + threadIdx.x;   // < NV by construction
        float fp = __ldg(&vm[v * 3 + 0]);
        float fh = __ldg(&vm[v * 3 + 1]);
        float fw = __ldg(&vm[v * 3 + 2]);
        int pix = (int)fp;
        int bin = (int)fh;
        int pos = atomicAdd(&d_cursor[bin], 1);
        if (pos < CAP) {
            d_pairs[bin * CAP + pos] = make_uint2((unsigned)(pix << 7), __float_as_uint(fw));
        } else {
            int o = atomicAdd(&d_ovf_cnt, 1);
            if (o < 4096)
                d_ovf[o] = make_uint4((unsigned)(pix << 7), __float_as_uint(fw),
                                      (unsigned)bin, 0u);
        }
    }
}

// -------- 2. hot kernel: latency-optimized segmented gather-reduce --------
// Block = 4 bins x 2 warps/bin. Pairs staged in smem (kills the 2-deep global
// dependency chain); warp h of a bin handles votes i%8 in {4h..4h+3} via its
// 4 quarter-warps. Lane owns 8 fp16 channels (LDG.128). fp32 accumulation.
__global__ void __launch_bounds__(256) gather_kernel(float* __restrict__ out) {
    __shared__ uint2 spairs[4][SCAPS];        // 6 KB
    __shared__ float sout[8][BC];             // 2 KB (per-warp partials)
    __shared__ int   scnt[4];
    int warp = threadIdx.x >> 5;
    int lane = threadIdx.x & 31;
    int b    = warp >> 1;                     // bin slot 0..3
    int h    = warp & 1;                      // half 0/1
    int bin0 = blockIdx.x * 4;
    int bin  = bin0 + b;
    bool valid = bin < NB;

    int novf = d_ovf_cnt;                     // read early (0 in practice)
    if (valid && h == 0 && lane == 0) {
        int c = d_cursor[bin];
        scnt[b] = c;
        d_cursor[bin] = 0;                    // reset for next replay (sole reader)
    }
    if (blockIdx.x == 0 && threadIdx.x == 0) d_ovf_cnt = 0;
    __syncthreads();

    int cnt = valid ? scnt[b] : 0;
    if (cnt > CAP) cnt = CAP;
    int lim = cnt < SCAPS ? cnt : SCAPS;
    const uint2* pp = d_pairs + (size_t)bin * CAP;
    if (valid) {
        // both warps of the pair stage the bin's pairs (coalesced)
        for (int i = h * 32 + lane; i < lim; i += 64)
            spairs[b][i] = __ldg(&pp[i]);
    }
    __syncthreads();

    float acc[8] = {0.f, 0.f, 0.f, 0.f, 0.f, 0.f, 0.f, 0.f};
    if (valid) {
        int q   = lane >> 3;                  // quarter 0..3
        int sub = h * 4 + q;                  // vote phase 0..7
        const char* xb = (const char*)d_xh + (lane & 7) * 16;  // 8 fp16 channels
        int i = sub;
        #pragma unroll 4
        for (; i < lim; i += 8) {             // smem pairs: 1-deep global chain
            uint2 pw = spairs[b][i];
            uint4 xv = *(const uint4*)(xb + pw.x);
            float w = __uint_as_float(pw.y);
            float2 f0 = __half22float2(u2h2(xv.x));
            float2 f1 = __half22float2(u2h2(xv.y));
            float2 f2 = __half22float2(u2h2(xv.z));
            float2 f3 = __half22float2(u2h2(xv.w));
            acc[0] = fmaf(w, f0.x, acc[0]);
            acc[1] = fmaf(w, f0.y, acc[1]);
            acc[2] = fmaf(w, f1.x, acc[2]);
            acc[3] = fmaf(w, f1.y, acc[3]);
            acc[4] = fmaf(w, f2.x, acc[4]);
            acc[5] = fmaf(w, f2.y, acc[5]);
            acc[6] = fmaf(w, f3.x, acc[6]);
            acc[7] = fmaf(w, f3.y, acc[7]);
        }
        for (; i < cnt; i += 8) {             // beyond smem stage (rare)
            uint2 pw = __ldg(&pp[i]);
            uint4 xv = *(const uint4*)(xb + pw.x);
            float w = __uint_as_float(pw.y);
            float2 f0 = __half22float2(u2h2(xv.x));
            float2 f1 = __half22float2(u2h2(xv.y));
            float2 f2 = __half22float2(u2h2(xv.z));
            float2 f3 = __half22float2(u2h2(xv.w));
            acc[0] = fmaf(w, f0.x, acc[0]);
            acc[1] = fmaf(w, f0.y, acc[1]);
            acc[2] = fmaf(w, f1.x, acc[2]);
            acc[3] = fmaf(w, f1.y, acc[3]);
            acc[4] = fmaf(w, f2.x, acc[4]);
            acc[5] = fmaf(w, f2.y, acc[5]);
            acc[6] = fmaf(w, f3.x, acc[6]);
            acc[7] = fmaf(w, f3.y, acc[7]);
        }
        // inline overflow spill (statistically unreachable; correct if hit)
        if (novf > 4096) novf = 4096;
        for (int j = 0; j < novf; j++) {
            uint4 ov = d_ovf[j];
            if ((int)ov.z == bin && h == 0 && (lane >> 3) == 0) {
                uint4 xv = *(const uint4*)(xb + ov.x);
                float w = __uint_as_float(ov.y);
                float2 f0 = __half22float2(u2h2(xv.x));
                float2 f1 = __half22float2(u2h2(xv.y));
                float2 f2 = __half22float2(u2h2(xv.z));
                float2 f3 = __half22float2(u2h2(xv.w));
                acc[0] = fmaf(w, f0.x, acc[0]);
                acc[1] = fmaf(w, f0.y, acc[1]);
                acc[2] = fmaf(w, f1.x, acc[2]);
                acc[3] = fmaf(w, f1.y, acc[3]);
                acc[4] = fmaf(w, f2.x, acc[4]);
                acc[5] = fmaf(w, f2.y, acc[5]);
                acc[6] = fmaf(w, f3.x, acc[6]);
                acc[7] = fmaf(w, f3.y, acc[7]);
            }
        }
    }
    // combine the four quarter-warps within each warp
    #pragma unroll
    for (int k = 0; k < 8; k++) {
        acc[k] += __shfl_xor_sync(0xffffffffu, acc[k], 8);
        acc[k] += __shfl_xor_sync(0xffffffffu, acc[k], 16);
    }
    if (lane < 8) {
        #pragma unroll
        for (int k = 0; k < 8; k++) sout[warp][lane * 8 + k] = acc[k];
    }
    __syncthreads();
    // sum the two warp-halves, coalesced 16B-run stores
    int bb = threadIdx.x & 3;
    int c  = threadIdx.x >> 2;                // 0..63
    if (bin0 + bb < NB)
        out[c * NB + bin0 + bb] = sout[2 * bb][c] + sout[2 * bb + 1][c];
}

// -------- launch --------
extern "C" void kernel_launch(void* const* d_in, const int* in_sizes, int n_in,
                              void* d_out, int out_size) {
    const float* im = (const float*)d_in[0];
    const float* vm = (const float*)d_in[1];
    if (in_sizes[0] == NV * 3) { im = (const float*)d_in[1]; vm = (const float*)d_in[0]; }
    float* out = (float*)d_out;

    prep_kernel<<<TBLK + NV / 256, 256>>>(im, vm);
    gather_kernel<<<(NB + 3) / 4, 256>>>(out);
}

// round 11
// speedup vs baseline: 1.0886x; 1.0886x over previous
#include <cuda_runtime.h>
#include <cuda_fp16.h>
#include <cstdint>

#define IM_HW   16384          // 128*128 pixels
#define BC      64             // B*C channels
#define NB      10980          // 183*60 HT bins
#define NV      983040         // votes (= 3840*256 exactly)
#define CAP     256            // per-bin capacity (mean 89.5, sigma 9.4 -> 17 sigma)
#define TBLK    512            // transpose blocks in fused prep kernel

__device__ __forceinline__ __half2 u2h2(unsigned u) {
    union { unsigned u; __half2 h; } c; c.u = u; return c.h;
}
__device__ __forceinline__ unsigned h22u(__half2 h) {
    union { unsigned u; __half2 h; } c; c.h = h; return c.u;
}

// -------- persistent scratch (__device__ globals; zero-initialized) --------
__device__ uint4 d_xh[IM_HW * 8];             // fp16 image [pix][64ch] = 128B/row (2 MB)
__device__ int   d_cursor[NB];                // per-bin count; re-zeroed by gather
__device__ uint2 d_pairs[NB * CAP];           // (pix*128, bits(w_fp32)) per slot (22.5 MB)
__device__ int   d_ovf_cnt;
__device__ uint4 d_ovf[4096];                 // overflow spill (pixoff, wbits, bin, 0)

// -------- 1. fused prep: transpose+fp16 (blocks 0..511) || fill (blocks 512+) --------
__global__ void __launch_bounds__(256) prep_kernel(const float* __restrict__ im,
                                                   const float* __restrict__ vm) {
    if (blockIdx.x < TBLK) {
        __shared__ float tile[32][68];        // pitch 272B -> float4-aligned rows
        int pixbase = blockIdx.x * 32;
        int t  = threadIdx.x;
        int tx = t & 31;
        int ty = t >> 5;
        #pragma unroll
        for (int b0 = 0; b0 < BC; b0 += 8)
            tile[tx][b0 + ty] = im[(b0 + ty) * IM_HW + pixbase + tx];   // coalesced
        __syncthreads();
        int p  = t >> 3;
        int c0 = (t & 7) * 8;
        float4 a = *(float4*)&tile[p][c0];
        float4 b = *(float4*)&tile[p][c0 + 4];
        uint4 hv;
        hv.x = h22u(__float22half2_rn(make_float2(a.x, a.y)));
        hv.y = h22u(__float22half2_rn(make_float2(a.z, a.w)));
        hv.z = h22u(__float22half2_rn(make_float2(b.x, b.y)));
        hv.w = h22u(__float22half2_rn(make_float2(b.z, b.w)));
        *(uint4*)((char*)d_xh + (pixbase + p) * 128 + c0 * 2) = hv;
    } else {
        int v = (blockIdx.x - TBLK) * 256 + threadIdx.x;   // < NV by construction
        float fp = __ldg(&vm[v * 3 + 0]);
        float fh = __ldg(&vm[v * 3 + 1]);
        float fw = __ldg(&vm[v * 3 + 2]);
        int pix = (int)fp;
        int bin = (int)fh;
        int pos = atomicAdd(&d_cursor[bin], 1);
        if (pos < CAP) {
            d_pairs[bin * CAP + pos] = make_uint2((unsigned)(pix << 7), __float_as_uint(fw));
        } else {
            int o = atomicAdd(&d_ovf_cnt, 1);
            if (o < 4096)
                d_ovf[o] = make_uint4((unsigned)(pix << 7), __float_as_uint(fw),
                                      (unsigned)bin, 0u);
        }
    }
}

// 8-channel fp16 FMA into fp32 accumulators (function, not macro: no token
// substitution hazards on the .w member access)
__device__ __forceinline__ void fma8(float* acc, uint4 xv, float wgt) {
    float2 f0 = __half22float2(u2h2(xv.x));
    float2 f1 = __half22float2(u2h2(xv.y));
    float2 f2 = __half22float2(u2h2(xv.z));
    float2 f3 = __half22float2(u2h2(xv.w));
    acc[0] = fmaf(wgt, f0.x, acc[0]);
    acc[1] = fmaf(wgt, f0.y, acc[1]);
    acc[2] = fmaf(wgt, f1.x, acc[2]);
    acc[3] = fmaf(wgt, f1.y, acc[3]);
    acc[4] = fmaf(wgt, f2.x, acc[4]);
    acc[5] = fmaf(wgt, f2.y, acc[5]);
    acc[6] = fmaf(wgt, f3.x, acc[6]);
    acc[7] = fmaf(wgt, f3.y, acc[7]);
}

// -------- 2. hot kernel: MLP-4 segmented gather-reduce (fp16 x) --------
// One warp per bin; quarter q handles votes i%4==q; lane owns 8 channels
// (LDG.128). Batch-of-4: load 4 pair records, issue 4 independent 128B
// x-loads, then 32 FMAs — explicit MLP=4 (needs the (256,4) reg budget).
__global__ void __launch_bounds__(256, 4) gather_kernel(float* __restrict__ out) {
    __shared__ float sout[BC][8];             // [channel][bin-in-block]
    int warp = threadIdx.x >> 5;
    int lane = threadIdx.x & 31;
    int bin0 = blockIdx.x * 8;
    int bin  = bin0 + warp;

    float acc[8] = {0.f, 0.f, 0.f, 0.f, 0.f, 0.f, 0.f, 0.f};
    if (bin < NB) {
        int novf = d_ovf_cnt;
        int cnt  = d_cursor[bin];
        if (cnt > CAP) cnt = CAP;
        const uint2* pp = d_pairs + (size_t)bin * CAP;
        int q = lane >> 3;                    // 0..3
        const char* xb = (const char*)d_xh + (lane & 7) * 16;   // 8 fp16 channels
        int i = q;
        // batched: 4 votes per quarter in flight (16 votes/warp per batch)
        for (; i + 12 < cnt; i += 16) {
            uint2 p0 = __ldg(&pp[i]);
            uint2 p1 = __ldg(&pp[i + 4]);
            uint2 p2 = __ldg(&pp[i + 8]);
            uint2 p3 = __ldg(&pp[i + 12]);
            uint4 x0 = *(const uint4*)(xb + p0.x);
            uint4 x1 = *(const uint4*)(xb + p1.x);
            uint4 x2 = *(const uint4*)(xb + p2.x);
            uint4 x3 = *(const uint4*)(xb + p3.x);
            fma8(acc, x0, __uint_as_float(p0.y));
            fma8(acc, x1, __uint_as_float(p1.y));
            fma8(acc, x2, __uint_as_float(p2.y));
            fma8(acc, x3, __uint_as_float(p3.y));
        }
        for (; i < cnt; i += 4) {             // remainder (<=3 per quarter)
            uint2 pw = __ldg(&pp[i]);
            uint4 xv = *(const uint4*)(xb + pw.x);
            fma8(acc, xv, __uint_as_float(pw.y));
        }
        // inline overflow spill (statistically unreachable; correct if hit)
        if (novf > 4096) novf = 4096;
        for (int j = 0; j < novf; j++) {
            uint4 ov = d_ovf[j];
            if ((int)ov.z == bin && q == 0) {
                uint4 xv = *(const uint4*)(xb + ov.x);
                fma8(acc, xv, __uint_as_float(ov.y));
            }
        }
        if (lane == 0) d_cursor[bin] = 0;     // reset for next replay (sole reader)
    }
    if (blockIdx.x == 0 && threadIdx.x == 0) d_ovf_cnt = 0;

    // combine the four quarter-warps
    #pragma unroll
    for (int k = 0; k < 8; k++) {
        acc[k] += __shfl_xor_sync(0xffffffffu, acc[k], 8);
        acc[k] += __shfl_xor_sync(0xffffffffu, acc[k], 16);
    }
    if (lane < 8) {
        #pragma unroll
        for (int k = 0; k < 8; k++) sout[lane * 8 + k][warp] = acc[k];
    }
    __syncthreads();
    // coalesced write: thread t -> out[(t>>3)*NB + bin0 + (t&7)]
    int c = threadIdx.x >> 3;
    int b = threadIdx.x & 7;
    if (bin0 + b < NB) {
        out[c * NB + bin0 + b]        = sout[c][b];
        out[(c + 32) * NB + bin0 + b] = sout[c + 32][b];
    }
}

// -------- launch --------
extern "C" void kernel_launch(void* const* d_in, const int* in_sizes, int n_in,
                              void* d_out, int out_size) {
    const float* im = (const float*)d_in[0];
    const float* vm = (const float*)d_in[1];
    if (in_sizes[0] == NV * 3) { im = (const float*)d_in[1]; vm = (const float*)d_in[0]; }
    float* out = (float*)d_out;

    prep_kernel<<<TBLK + NV / 256, 256>>>(im, vm);
    gather_kernel<<<(NB + 7) / 8, 256>>>(out);
}